// round 12
// baseline (speedup 1.0000x reference)
#include <cuda_runtime.h>
#include <cuda_fp16.h>
#include <stdint.h>

#define N_NODES 100000
#define N_EDGES 1600000
#define HID 128
#define OUTD 64

#define SCAN_B 98          // ceil(100000 / 1024)

// ---------------- static device scratch (no allocations allowed) ----------
__device__ __align__(16) int g_deg[N_NODES];
__device__ float g_dinv[N_NODES];
__device__ int   g_ptr[N_NODES + 1];
__device__ int   g_fill[N_NODES];
__device__ int   g_is64;                                      // edge dtype flag
__device__ __align__(16) unsigned long long g_edges[N_EDGES]; // {norm<<32 | col}
// y-state stored fp16 (fp32 math everywhere); one node row = 64*2 = 128 B.
__device__ __align__(16) __half g_y0[N_NODES * OUTD];
__device__ __align__(16) __half g_y1[N_NODES * OUTD];
__device__ __align__(16) __half g_y2[N_NODES * OUTD];

// ---------------- init: zero degree + edge-dtype probe (fused) ------------
__global__ void k_init(const unsigned long long* __restrict__ p) {
    int i = blockIdx.x * blockDim.x + threadIdx.x;
    if (i < N_NODES) g_deg[i] = 0;
    if (blockIdx.x == 0) {
        __shared__ int big;
        if (threadIdx.x == 0) big = 0;
        __syncthreads();
        for (int k = threadIdx.x; k < 2048; k += blockDim.x)
            if (p[k] >= (unsigned long long)N_NODES) big = 1;
        __syncthreads();
        if (threadIdx.x == 0) g_is64 = big ? 0 : 1;
    }
}

// ---------------- build: degree histogram (2 edges / thread) --------------
__global__ void k_hist(const void* __restrict__ eiv) {
    int e = (blockIdx.x * blockDim.x + threadIdx.x) * 2;
    if (e >= N_EDGES) return;
    int r0, r1;
    if (g_is64) {
        longlong2 rr = __ldg((const longlong2*)((const long long*)eiv + e));
        r0 = (int)rr.x; r1 = (int)rr.y;
    } else {
        int2 rr = __ldg((const int2*)((const int*)eiv + e));
        r0 = rr.x; r1 = rr.y;
    }
    if (r0 >= 0 && r0 < N_NODES) atomicAdd(&g_deg[r0], 1);
    if (e + 1 < N_EDGES && r1 >= 0 && r1 < N_NODES) atomicAdd(&g_deg[r1], 1);
}

// ------- build: SINGLE-kernel scan -> ptr + fill + dinv -------------------
// Each block independently reduces deg[0 .. blk*1024) for its offset (L2-
// resident, ~19 MB total), then does a local scan of its own 1024 degrees.
__global__ void __launch_bounds__(1024) k_scan() {
    __shared__ int red[32];
    __shared__ int warp_sums[32];
    __shared__ int s_boff;
    const int t = threadIdx.x;
    const int limit = blockIdx.x * 1024;           // multiple of 4096 bytes

    // --- block offset: sum over all preceding degrees ---
    int o = 0;
    for (int i = t * 4; i < limit; i += 4096) {
        int4 d = *(const int4*)(g_deg + i);
        o += d.x + d.y + d.z + d.w;
    }
    #pragma unroll
    for (int s = 16; s > 0; s >>= 1) o += __shfl_down_sync(0xffffffffu, o, s);
    if ((t & 31) == 0) red[t >> 5] = o;
    __syncthreads();
    if (t < 32) {
        int v = red[t];
        #pragma unroll
        for (int s = 16; s > 0; s >>= 1) v += __shfl_down_sync(0xffffffffu, v, s);
        if (t == 0) s_boff = v;
    }
    __syncthreads();
    const int boff = s_boff;

    // --- local inclusive scan of this block's 1024 degrees ---
    int i = limit + t;
    int d = (i < N_NODES) ? g_deg[i] : 0;
    int incl = d;
    int lane = t & 31;
    #pragma unroll
    for (int s = 1; s < 32; s <<= 1) {
        int u = __shfl_up_sync(0xffffffffu, incl, s);
        if (lane >= s) incl += u;
    }
    if (lane == 31) warp_sums[t >> 5] = incl;
    __syncthreads();
    if (t < 32) {
        int v = warp_sums[t];
        #pragma unroll
        for (int s = 1; s < 32; s <<= 1) {
            int u = __shfl_up_sync(0xffffffffu, v, s);
            if (t >= s) v += u;
        }
        warp_sums[t] = v;
    }
    __syncthreads();
    int wbase = (t >= 32) ? warp_sums[(t >> 5) - 1] : 0;
    int excl = boff + wbase + incl - d;
    if (i < N_NODES) {
        g_ptr[i]  = excl;
        g_fill[i] = excl;
        g_dinv[i] = rsqrtf((float)(d < 1 ? 1 : d));
    }
    if (blockIdx.x == SCAN_B - 1 && t == 0)
        g_ptr[N_NODES] = boff + warp_sums[31];
}

// ---------------- build: scatter edges into CSR (2 edges / thread) --------
__global__ void k_scatter(const void* __restrict__ eiv) {
    int e = (blockIdx.x * blockDim.x + threadIdx.x) * 2;
    if (e >= N_EDGES) return;
    int r0, r1, c0, c1;
    if (g_is64) {
        longlong2 rr = __ldg((const longlong2*)((const long long*)eiv + e));
        longlong2 cc = __ldg((const longlong2*)((const long long*)eiv + N_EDGES + e));
        r0 = (int)rr.x; r1 = (int)rr.y; c0 = (int)cc.x; c1 = (int)cc.y;
    } else {
        int2 rr = __ldg((const int2*)((const int*)eiv + e));
        int2 cc = __ldg((const int2*)((const int*)eiv + N_EDGES + e));
        r0 = rr.x; r1 = rr.y; c0 = cc.x; c1 = cc.y;
    }
    if (r0 >= 0 && r0 < N_NODES && c0 >= 0 && c0 < N_NODES) {
        float w = g_dinv[r0] * g_dinv[c0];
        int slot = atomicAdd(&g_fill[r0], 1);
        g_edges[slot] = ((unsigned long long)__float_as_uint(w) << 32) |
                        (unsigned long long)(unsigned)c0;
    }
    if (e + 1 < N_EDGES && r1 >= 0 && r1 < N_NODES && c1 >= 0 && c1 < N_NODES) {
        float w = g_dinv[r1] * g_dinv[c1];
        int slot = atomicAdd(&g_fill[r1], 1);
        g_edges[slot] = ((unsigned long long)__float_as_uint(w) << 32) |
                        (unsigned long long)(unsigned)c1;
    }
}

// ---------------- y0 = x @ W^T (shared-staged x tile, fp16 out) -----------
#define GTILE 16
#define XROW 136   // padded row stride in floats
__global__ void __launch_bounds__(128) k_gemm(const float* __restrict__ x,
                                              const float* __restrict__ W) {
    __shared__ float sx[GTILE * XROW];   // 8.5 KB

    const int tid   = threadIdx.x;
    const int warp  = tid >> 5;
    const int lane  = tid & 31;
    const int o     = warp * 16 + (lane & 15);
    const int khalf = lane >> 4;          // 0 or 1

    float4 wr[16];
    const float4* Wv = (const float4*)(W + o * HID + khalf * 64);
#pragma unroll
    for (int i = 0; i < 16; i++) wr[i] = Wv[i];

    const int base = blockIdx.x * GTILE;
    const float4* xg = (const float4*)(x + (long long)base * HID);
#pragma unroll
    for (int j = 0; j < 4; j++) {
        int f4 = tid + j * 128;                   // 0..511
        int t  = f4 >> 5;
        int k  = f4 & 31;
        float4 v = xg[f4];
        int word = t * XROW + ((k < 16) ? (k * 4) : (68 + (k - 16) * 4));
        *(float4*)(sx + word) = v;
    }
    __syncthreads();

#pragma unroll 1
    for (int t = 0; t < GTILE; t++) {
        const float4* xv = (const float4*)(sx + t * XROW + khalf * 68);
        float ax = 0.f, ay = 0.f, az = 0.f, aw = 0.f;
#pragma unroll
        for (int i = 0; i < 16; i++) {
            float4 xi = xv[i];
            ax += xi.x * wr[i].x;
            ay += xi.y * wr[i].y;
            az += xi.z * wr[i].z;
            aw += xi.w * wr[i].w;
        }
        float s = (ax + ay) + (az + aw);
        s += __shfl_down_sync(0xffffffffu, s, 16);
        if (khalf == 0) g_y0[(base + t) * OUTD + o] = __float2half_rn(s);
    }
}

// ---------------- propagate: WARP-PER-NODE, lane = half2 (2 dims) ---------
// One 128-B row per gather instruction; zero cross-node divergence; 4-deep
// pipeline (8 outstanding loads/warp) with ~30 regs -> full occupancy.
// Tail uses zero edges (w=0, c=0): harmless row-0 gathers.
__device__ __forceinline__ void wprop(const __half2* __restrict__ sv,
                                      int beg, int end, int l,
                                      float& ax, float& ay) {
    int n = end - beg;
    if (n <= 0) return;
    unsigned long long c0, c1, c2, c3;
    c0 = __ldg(&g_edges[beg]);
    c1 = (beg + 1 < end) ? __ldg(&g_edges[beg + 1]) : 0ull;
    c2 = (beg + 2 < end) ? __ldg(&g_edges[beg + 2]) : 0ull;
    c3 = (beg + 3 < end) ? __ldg(&g_edges[beg + 3]) : 0ull;
    int e = beg + 4;
    int nb = (n + 3) >> 2;
#pragma unroll 1
    for (int b = 0; b < nb; b++) {
        __half2 u0 = __ldg(&sv[(unsigned)(c0 & 0xffffffffull) * 32u + l]);
        __half2 u1 = __ldg(&sv[(unsigned)(c1 & 0xffffffffull) * 32u + l]);
        __half2 u2 = __ldg(&sv[(unsigned)(c2 & 0xffffffffull) * 32u + l]);
        __half2 u3 = __ldg(&sv[(unsigned)(c3 & 0xffffffffull) * 32u + l]);
        unsigned long long n0 = 0, n1 = 0, n2 = 0, n3 = 0;
        if (e     < end) n0 = __ldg(&g_edges[e]);
        if (e + 1 < end) n1 = __ldg(&g_edges[e + 1]);
        if (e + 2 < end) n2 = __ldg(&g_edges[e + 2]);
        if (e + 3 < end) n3 = __ldg(&g_edges[e + 3]);
        float2 f0 = __half22float2(u0);
        float2 f1 = __half22float2(u1);
        float2 f2 = __half22float2(u2);
        float2 f3 = __half22float2(u3);
        float w0 = __uint_as_float((unsigned)(c0 >> 32));
        float w1 = __uint_as_float((unsigned)(c1 >> 32));
        float w2 = __uint_as_float((unsigned)(c2 >> 32));
        float w3 = __uint_as_float((unsigned)(c3 >> 32));
        ax = fmaf(w0, f0.x, ax); ay = fmaf(w0, f0.y, ay);
        ax = fmaf(w1, f1.x, ax); ay = fmaf(w1, f1.y, ay);
        ax = fmaf(w2, f2.x, ax); ay = fmaf(w2, f2.y, ay);
        ax = fmaf(w3, f3.x, ax); ay = fmaf(w3, f3.y, ay);
        c0 = n0; c1 = n1; c2 = n2; c3 = n3;
        e += 4;
    }
}

// LAYER 0: y1 = P(y0)   LAYER 1: y2 = P(y1)
template <int LAYER>
__global__ void __launch_bounds__(256) k_prop_mid() {
    const __half2* __restrict__ src = (const __half2*)((LAYER == 0) ? g_y0 : g_y1);
    __half2*       __restrict__ dst = (__half2*)((LAYER == 0) ? g_y1 : g_y2);
    int warp = threadIdx.x >> 5;
    int l    = threadIdx.x & 31;
    int v    = blockIdx.x * 8 + warp;          // grid = 12500, exact
    float ax = 0.f, ay = 0.f;
    wprop(src, g_ptr[v], g_ptr[v + 1], l, ax, ay);
    dst[v * 32 + l] = __floats2half2_rn(ax, ay);
}

// final: out = (y0 + y1 + y2 + P(y2)) * 0.25 + b   (fp32 output)
__global__ void __launch_bounds__(256) k_prop_final(const float* __restrict__ bvec,
                                                    float* __restrict__ out) {
    int warp = threadIdx.x >> 5;
    int l    = threadIdx.x & 31;
    int v    = blockIdx.x * 8 + warp;
    float ax = 0.f, ay = 0.f;
    wprop((const __half2*)g_y2, g_ptr[v], g_ptr[v + 1], l, ax, ay);
    float2 a0 = __half22float2(((const __half2*)g_y0)[v * 32 + l]);
    float2 a1 = __half22float2(((const __half2*)g_y1)[v * 32 + l]);
    float2 a2 = __half22float2(((const __half2*)g_y2)[v * 32 + l]);
    float2 bb = ((const float2*)bvec)[l];
    float2 r;
    r.x = (a0.x + a1.x + a2.x + ax) * 0.25f + bb.x;
    r.y = (a0.y + a1.y + a2.y + ay) * 0.25f + bb.y;
    ((float2*)out)[v * 32 + l] = r;
}

// ---------------- launcher ------------------------------------------------
extern "C" void kernel_launch(void* const* d_in, const int* in_sizes, int n_in,
                              void* d_out, int out_size) {
    const float* x = nullptr;
    const float* W = nullptr;
    const float* b = nullptr;
    const void*  ei = nullptr;
    for (int i = 0; i < n_in; i++) {
        long long s = in_sizes[i];
        if      (s == (long long)N_NODES * HID) x = (const float*)d_in[i];
        else if (s == (long long)OUTD * HID)    W = (const float*)d_in[i];
        else if (s == (long long)OUTD)          b = (const float*)d_in[i];
        else ei = d_in[i];
    }
    if (!x)  x  = (const float*)d_in[0];
    if (!ei) ei = d_in[1];
    if (!W)  W  = (const float*)d_in[2];
    if (!b)  b  = (const float*)d_in[3];

    float* out = (float*)d_out;

    const int TB = 256;
    const int eb2 = (N_EDGES / 2 + TB - 1) / TB;  // 3125 (2 edges/thread)
    const int nb  = (N_NODES + TB - 1) / TB;      // 391
    const int pw  = N_NODES / 8;                  // 12500 (warp-per-node)

    // Persistent side-stream handles: created ONCE on the first call (the
    // correctness run, outside capture); reused by every later call/capture.
    static cudaStream_t s2 = nullptr;
    static cudaEvent_t evFork = nullptr, evJoin = nullptr;
    if (!s2) {
        cudaStreamCreateWithFlags(&s2, cudaStreamNonBlocking);
        cudaEventCreateWithFlags(&evFork, cudaEventDisableTiming);
        cudaEventCreateWithFlags(&evJoin, cudaEventDisableTiming);
    }

    // Fork: GEMM overlaps the CSR build.
    cudaEventRecord(evFork, 0);
    cudaStreamWaitEvent(s2, evFork, 0);
    k_gemm<<<N_NODES / GTILE, 128, 0, s2>>>(x, W);   // y0 = x @ W^T
    cudaEventRecord(evJoin, s2);

    // CSR build on the main stream (overlaps with GEMM)
    k_init<<<nb, TB>>>((const unsigned long long*)ei);  // zero deg + dtype probe
    k_hist<<<eb2, TB>>>(ei);
    k_scan<<<SCAN_B, 1024>>>();                         // ptr + fill + dinv (one kernel)
    k_scatter<<<eb2, TB>>>(ei);

    cudaStreamWaitEvent(0, evJoin, 0);       // join: props need y0 + CSR

    // 3 propagation layers in 64-dim fp16 space (warp-per-node)
    k_prop_mid<0><<<pw, TB>>>();      // y1 = P(y0)
    k_prop_mid<1><<<pw, TB>>>();      // y2 = P(y1)
    k_prop_final<<<pw, TB>>>(b, out); // out = (y0+y1+y2+P(y2))/4 + b
}

// round 13
// speedup vs baseline: 1.0776x; 1.0776x over previous
#include <cuda_runtime.h>
#include <cuda_fp16.h>
#include <stdint.h>

#define N_NODES 100000
#define N_EDGES 1600000
#define HID 128
#define OUTD 64

#define SCAN_B 98          // ceil(100000 / 1024)

// ---------------- static device scratch (no allocations allowed) ----------
__device__ __align__(16) int g_deg[N_NODES];
__device__ float g_dinv[N_NODES];
__device__ int   g_ptr[N_NODES + 1];
__device__ int   g_fill[N_NODES];
__device__ int   g_is64;                                      // edge dtype flag
__device__ __align__(16) unsigned long long g_edges[N_EDGES]; // {norm<<32 | col}
// y-state stored fp16 (fp32 math everywhere); one node row = 64*2 = 128 B.
__device__ __align__(16) __half g_y0[N_NODES * OUTD];
__device__ __align__(16) __half g_y1[N_NODES * OUTD];
__device__ __align__(16) __half g_y2[N_NODES * OUTD];

// ---------------- init: zero degree + edge-dtype probe (fused) ------------
__global__ void k_init(const unsigned long long* __restrict__ p) {
    int i = blockIdx.x * blockDim.x + threadIdx.x;
    if (i < N_NODES) g_deg[i] = 0;
    if (blockIdx.x == 0) {
        __shared__ int big;
        if (threadIdx.x == 0) big = 0;
        __syncthreads();
        for (int k = threadIdx.x; k < 2048; k += blockDim.x)
            if (p[k] >= (unsigned long long)N_NODES) big = 1;
        __syncthreads();
        if (threadIdx.x == 0) g_is64 = big ? 0 : 1;
    }
}

// ---------------- build: degree histogram (2 edges / thread) --------------
__global__ void k_hist(const void* __restrict__ eiv) {
    int e = (blockIdx.x * blockDim.x + threadIdx.x) * 2;
    if (e >= N_EDGES) return;
    int r0, r1;
    if (g_is64) {
        longlong2 rr = __ldg((const longlong2*)((const long long*)eiv + e));
        r0 = (int)rr.x; r1 = (int)rr.y;
    } else {
        int2 rr = __ldg((const int2*)((const int*)eiv + e));
        r0 = rr.x; r1 = rr.y;
    }
    if (r0 >= 0 && r0 < N_NODES) atomicAdd(&g_deg[r0], 1);
    if (e + 1 < N_EDGES && r1 >= 0 && r1 < N_NODES) atomicAdd(&g_deg[r1], 1);
}

// ------- build: SINGLE-kernel scan -> ptr + fill + dinv -------------------
// Each block independently reduces deg[0 .. blk*1024) for its offset (L2-
// resident), then locally scans its own 1024 degrees.
__global__ void __launch_bounds__(1024) k_scan() {
    __shared__ int red[32];
    __shared__ int warp_sums[32];
    __shared__ int s_boff;
    const int t = threadIdx.x;
    const int limit = blockIdx.x * 1024;

    int o = 0;
    for (int i = t * 4; i < limit; i += 4096) {
        int4 d = *(const int4*)(g_deg + i);
        o += d.x + d.y + d.z + d.w;
    }
    #pragma unroll
    for (int s = 16; s > 0; s >>= 1) o += __shfl_down_sync(0xffffffffu, o, s);
    if ((t & 31) == 0) red[t >> 5] = o;
    __syncthreads();
    if (t < 32) {
        int v = red[t];
        #pragma unroll
        for (int s = 16; s > 0; s >>= 1) v += __shfl_down_sync(0xffffffffu, v, s);
        if (t == 0) s_boff = v;
    }
    __syncthreads();
    const int boff = s_boff;

    int i = limit + t;
    int d = (i < N_NODES) ? g_deg[i] : 0;
    int incl = d;
    int lane = t & 31;
    #pragma unroll
    for (int s = 1; s < 32; s <<= 1) {
        int u = __shfl_up_sync(0xffffffffu, incl, s);
        if (lane >= s) incl += u;
    }
    if (lane == 31) warp_sums[t >> 5] = incl;
    __syncthreads();
    if (t < 32) {
        int v = warp_sums[t];
        #pragma unroll
        for (int s = 1; s < 32; s <<= 1) {
            int u = __shfl_up_sync(0xffffffffu, v, s);
            if (t >= s) v += u;
        }
        warp_sums[t] = v;
    }
    __syncthreads();
    int wbase = (t >= 32) ? warp_sums[(t >> 5) - 1] : 0;
    int excl = boff + wbase + incl - d;
    if (i < N_NODES) {
        g_ptr[i]  = excl;
        g_fill[i] = excl;
        g_dinv[i] = rsqrtf((float)(d < 1 ? 1 : d));
    }
    if (blockIdx.x == SCAN_B - 1 && t == 0)
        g_ptr[N_NODES] = boff + warp_sums[31];
}

// ---------------- build: scatter edges into CSR (2 edges / thread) --------
__global__ void k_scatter(const void* __restrict__ eiv) {
    int e = (blockIdx.x * blockDim.x + threadIdx.x) * 2;
    if (e >= N_EDGES) return;
    int r0, r1, c0, c1;
    if (g_is64) {
        longlong2 rr = __ldg((const longlong2*)((const long long*)eiv + e));
        longlong2 cc = __ldg((const longlong2*)((const long long*)eiv + N_EDGES + e));
        r0 = (int)rr.x; r1 = (int)rr.y; c0 = (int)cc.x; c1 = (int)cc.y;
    } else {
        int2 rr = __ldg((const int2*)((const int*)eiv + e));
        int2 cc = __ldg((const int2*)((const int*)eiv + N_EDGES + e));
        r0 = rr.x; r1 = rr.y; c0 = cc.x; c1 = cc.y;
    }
    if (r0 >= 0 && r0 < N_NODES && c0 >= 0 && c0 < N_NODES) {
        float w = g_dinv[r0] * g_dinv[c0];
        int slot = atomicAdd(&g_fill[r0], 1);
        g_edges[slot] = ((unsigned long long)__float_as_uint(w) << 32) |
                        (unsigned long long)(unsigned)c0;
    }
    if (e + 1 < N_EDGES && r1 >= 0 && r1 < N_NODES && c1 >= 0 && c1 < N_NODES) {
        float w = g_dinv[r1] * g_dinv[c1];
        int slot = atomicAdd(&g_fill[r1], 1);
        g_edges[slot] = ((unsigned long long)__float_as_uint(w) << 32) |
                        (unsigned long long)(unsigned)c1;
    }
}

// ---------------- y0 = x @ W^T (shared-staged x tile, fp16 out) -----------
#define GTILE 16
#define XROW 136   // padded row stride in floats
__global__ void __launch_bounds__(128) k_gemm(const float* __restrict__ x,
                                              const float* __restrict__ W) {
    __shared__ float sx[GTILE * XROW];   // 8.5 KB

    const int tid   = threadIdx.x;
    const int warp  = tid >> 5;
    const int lane  = tid & 31;
    const int o     = warp * 16 + (lane & 15);
    const int khalf = lane >> 4;          // 0 or 1

    float4 wr[16];
    const float4* Wv = (const float4*)(W + o * HID + khalf * 64);
#pragma unroll
    for (int i = 0; i < 16; i++) wr[i] = Wv[i];

    const int base = blockIdx.x * GTILE;
    const float4* xg = (const float4*)(x + (long long)base * HID);
#pragma unroll
    for (int j = 0; j < 4; j++) {
        int f4 = tid + j * 128;                   // 0..511
        int t  = f4 >> 5;
        int k  = f4 & 31;
        float4 v = xg[f4];
        int word = t * XROW + ((k < 16) ? (k * 4) : (68 + (k - 16) * 4));
        *(float4*)(sx + word) = v;
    }
    __syncthreads();

#pragma unroll 1
    for (int t = 0; t < GTILE; t++) {
        const float4* xv = (const float4*)(sx + t * XROW + khalf * 68);
        float ax = 0.f, ay = 0.f, az = 0.f, aw = 0.f;
#pragma unroll
        for (int i = 0; i < 16; i++) {
            float4 xi = xv[i];
            ax += xi.x * wr[i].x;
            ay += xi.y * wr[i].y;
            az += xi.z * wr[i].z;
            aw += xi.w * wr[i].w;
        }
        float s = (ax + ay) + (az + aw);
        s += __shfl_down_sync(0xffffffffu, s, 16);
        if (khalf == 0) g_y0[(base + t) * OUTD + o] = __float2half_rn(s);
    }
}

// ---------------- propagate core: 4-deep pipelined fp16 gathers -----------
// (R10 structure — best measured.) 16 lanes per node; lane l covers dims
// [4l, 4l+4) = one uint2. Tail uses zero edges (w=0, c=0).
__device__ __forceinline__ void h_fma(uint2 u, float w,
                                      float& ax, float& ay, float& az, float& aw) {
    float2 f0 = __half22float2(*(const __half2*)&u.x);
    float2 f1 = __half22float2(*(const __half2*)&u.y);
    ax = fmaf(w, f0.x, ax); ay = fmaf(w, f0.y, ay);
    az = fmaf(w, f1.x, az); aw = fmaf(w, f1.y, aw);
}

__device__ __forceinline__ void prop_accum(const __half* __restrict__ src,
                                           int beg, int end, int l,
                                           float& ax, float& ay,
                                           float& az, float& aw) {
    int n = end - beg;
    if (n <= 0) return;
    const uint2* __restrict__ sv = (const uint2*)src;   // 16 uint2 per row

    unsigned long long c0, c1, c2, c3;
    c0 = __ldg(&g_edges[beg]);
    c1 = (beg + 1 < end) ? __ldg(&g_edges[beg + 1]) : 0ull;
    c2 = (beg + 2 < end) ? __ldg(&g_edges[beg + 2]) : 0ull;
    c3 = (beg + 3 < end) ? __ldg(&g_edges[beg + 3]) : 0ull;
    int e = beg + 4;
    int nb = (n + 3) >> 2;
#pragma unroll 1
    for (int b = 0; b < nb; b++) {
        uint2 u0 = __ldg(&sv[(unsigned)(c0 & 0xffffffffull) * 16u + l]);
        uint2 u1 = __ldg(&sv[(unsigned)(c1 & 0xffffffffull) * 16u + l]);
        uint2 u2 = __ldg(&sv[(unsigned)(c2 & 0xffffffffull) * 16u + l]);
        uint2 u3 = __ldg(&sv[(unsigned)(c3 & 0xffffffffull) * 16u + l]);
        unsigned long long n0 = 0, n1 = 0, n2 = 0, n3 = 0;
        if (e     < end) n0 = __ldg(&g_edges[e]);
        if (e + 1 < end) n1 = __ldg(&g_edges[e + 1]);
        if (e + 2 < end) n2 = __ldg(&g_edges[e + 2]);
        if (e + 3 < end) n3 = __ldg(&g_edges[e + 3]);
        h_fma(u0, __uint_as_float((unsigned)(c0 >> 32)), ax, ay, az, aw);
        h_fma(u1, __uint_as_float((unsigned)(c1 >> 32)), ax, ay, az, aw);
        h_fma(u2, __uint_as_float((unsigned)(c2 >> 32)), ax, ay, az, aw);
        h_fma(u3, __uint_as_float((unsigned)(c3 >> 32)), ax, ay, az, aw);
        c0 = n0; c1 = n1; c2 = n2; c3 = n3;
        e += 4;
    }
}

// Props use 1024-thread blocks: same warp count chip-wide, but oe (CTAs/SM)
// drops 8 -> 2, collapsing the cross-CTA L1tex-queue spread
// (spr = 1.10 + 25*(oe*MLP_p1 - 16)/T_CTA; oe*MLP_p1: 64 -> 16 = threshold).
#define PROP_TB 1024
#define PROP_GRID ((N_NODES * 16 + PROP_TB - 1) / PROP_TB)   // 1563

// LAYER 0: y1 = P(y0)   LAYER 1: y2 = P(y1)
template <int LAYER>
__global__ void __launch_bounds__(PROP_TB) k_prop_mid() {
    const __half* __restrict__ src = (LAYER == 0) ? g_y0 : g_y1;
    __half*       __restrict__ dst = (LAYER == 0) ? g_y1 : g_y2;
    int gid = blockIdx.x * PROP_TB + threadIdx.x;
    int v = gid >> 4;
    int l = gid & 15;
    if (v >= N_NODES) return;
    float ax = 0.f, ay = 0.f, az = 0.f, aw = 0.f;
    prop_accum(src, g_ptr[v], g_ptr[v + 1], l, ax, ay, az, aw);
    __half2 h0 = __floats2half2_rn(ax, ay);
    __half2 h1 = __floats2half2_rn(az, aw);
    uint2 o;
    o.x = *(const unsigned*)&h0;
    o.y = *(const unsigned*)&h1;
    *((uint2*)(dst + v * OUTD) + l) = o;
}

// final: out = (y0 + y1 + y2 + P(y2)) * 0.25 + b   (fp32 output)
__global__ void __launch_bounds__(PROP_TB) k_prop_final(const float* __restrict__ bvec,
                                                        float* __restrict__ out) {
    int gid = blockIdx.x * PROP_TB + threadIdx.x;
    int v = gid >> 4;
    int l = gid & 15;
    if (v >= N_NODES) return;
    float ax = 0.f, ay = 0.f, az = 0.f, aw = 0.f;
    prop_accum(g_y2, g_ptr[v], g_ptr[v + 1], l, ax, ay, az, aw);
    uint2 u0 = *((const uint2*)(g_y0 + v * OUTD) + l);
    uint2 u1 = *((const uint2*)(g_y1 + v * OUTD) + l);
    uint2 u2 = *((const uint2*)(g_y2 + v * OUTD) + l);
    float2 a0  = __half22float2(*(const __half2*)&u0.x);
    float2 a0h = __half22float2(*(const __half2*)&u0.y);
    float2 a1  = __half22float2(*(const __half2*)&u1.x);
    float2 a1h = __half22float2(*(const __half2*)&u1.y);
    float2 a2  = __half22float2(*(const __half2*)&u2.x);
    float2 a2h = __half22float2(*(const __half2*)&u2.y);
    float b0 = bvec[l * 4 + 0], b1 = bvec[l * 4 + 1];
    float b2 = bvec[l * 4 + 2], b3 = bvec[l * 4 + 3];
    float4 r;
    r.x = (a0.x + a1.x + a2.x + ax) * 0.25f + b0;
    r.y = (a0.y + a1.y + a2.y + ay) * 0.25f + b1;
    r.z = (a0h.x + a1h.x + a2h.x + az) * 0.25f + b2;
    r.w = (a0h.y + a1h.y + a2h.y + aw) * 0.25f + b3;
    *(float4*)(out + v * OUTD + l * 4) = r;
}

// ---------------- launcher ------------------------------------------------
extern "C" void kernel_launch(void* const* d_in, const int* in_sizes, int n_in,
                              void* d_out, int out_size) {
    const float* x = nullptr;
    const float* W = nullptr;
    const float* b = nullptr;
    const void*  ei = nullptr;
    for (int i = 0; i < n_in; i++) {
        long long s = in_sizes[i];
        if      (s == (long long)N_NODES * HID) x = (const float*)d_in[i];
        else if (s == (long long)OUTD * HID)    W = (const float*)d_in[i];
        else if (s == (long long)OUTD)          b = (const float*)d_in[i];
        else ei = d_in[i];
    }
    if (!x)  x  = (const float*)d_in[0];
    if (!ei) ei = d_in[1];
    if (!W)  W  = (const float*)d_in[2];
    if (!b)  b  = (const float*)d_in[3];

    float* out = (float*)d_out;

    const int TB = 256;
    const int eb2 = (N_EDGES / 2 + TB - 1) / TB;  // 3125 (2 edges/thread)
    const int nb  = (N_NODES + TB - 1) / TB;      // 391

    // Persistent side-stream handles: created ONCE on the first call (the
    // correctness run, outside capture); reused by every later call/capture.
    static cudaStream_t s2 = nullptr;
    static cudaEvent_t evFork = nullptr, evJoin = nullptr;
    if (!s2) {
        cudaStreamCreateWithFlags(&s2, cudaStreamNonBlocking);
        cudaEventCreateWithFlags(&evFork, cudaEventDisableTiming);
        cudaEventCreateWithFlags(&evJoin, cudaEventDisableTiming);
    }

    // Fork: GEMM overlaps the CSR build.
    cudaEventRecord(evFork, 0);
    cudaStreamWaitEvent(s2, evFork, 0);
    k_gemm<<<N_NODES / GTILE, 128, 0, s2>>>(x, W);   // y0 = x @ W^T
    cudaEventRecord(evJoin, s2);

    // CSR build on the main stream (overlaps with GEMM)
    k_init<<<nb, TB>>>((const unsigned long long*)ei);  // zero deg + dtype probe
    k_hist<<<eb2, TB>>>(ei);
    k_scan<<<SCAN_B, 1024>>>();                         // ptr + fill + dinv
    k_scatter<<<eb2, TB>>>(ei);

    cudaStreamWaitEvent(0, evJoin, 0);       // join: props need y0 + CSR

    // 3 propagation layers in 64-dim fp16 space (1024-thread blocks)
    k_prop_mid<0><<<PROP_GRID, PROP_TB>>>();      // y1 = P(y0)
    k_prop_mid<1><<<PROP_GRID, PROP_TB>>>();      // y2 = P(y1)
    k_prop_final<<<PROP_GRID, PROP_TB>>>(b, out); // out = (y0+y1+y2+P(y2))/4 + b
}

// round 14
// speedup vs baseline: 1.1466x; 1.0641x over previous
#include <cuda_runtime.h>
#include <cuda_fp16.h>
#include <stdint.h>

#define N_NODES 100000
#define N_EDGES 1600000
#define HID 128
#define OUTD 64

#define SCAN_B 98          // ceil(100000 / 1024)

// ---------------- static device scratch (no allocations allowed) ----------
__device__ __align__(16) int g_deg[N_NODES];
__device__ float g_dinv[N_NODES + 1];     // +1: pad col reads dinv[N]=0
__device__ float g_rdinv[N_NODES];        // sqrt(max(deg,1)) = 1/dinv
__device__ int   g_ptr[N_NODES + 1];
__device__ int   g_fill[N_NODES];
__device__ int   g_bsum[SCAN_B];
__device__ int   g_boff[SCAN_B];
__device__ int   g_is64;                                   // edge dtype flag
__device__ __align__(16) int g_ecol[N_EDGES];              // 4-byte edges!
// z-state fp16; one node row = 64*2 = 128 B. Extra row N_NODES is the
// always-zero pad row (static zero-init, never written).
__device__ __align__(16) __half g_y0[(N_NODES + 1) * OUTD];
__device__ __align__(16) __half g_z1[(N_NODES + 1) * OUTD];
__device__ __align__(16) __half g_z2[(N_NODES + 1) * OUTD];

// ---------------- init: zero degree + edge-dtype probe (fused) ------------
__global__ void k_init(const unsigned long long* __restrict__ p) {
    int i = blockIdx.x * blockDim.x + threadIdx.x;
    if (i < N_NODES) g_deg[i] = 0;
    if (blockIdx.x == 0) {
        __shared__ int big;
        if (threadIdx.x == 0) big = 0;
        __syncthreads();
        for (int k = threadIdx.x; k < 2048; k += blockDim.x)
            if (p[k] >= (unsigned long long)N_NODES) big = 1;
        __syncthreads();
        if (threadIdx.x == 0) g_is64 = big ? 0 : 1;
    }
}

// ---------------- build: degree histogram (2 edges / thread) --------------
__global__ void k_hist(const void* __restrict__ eiv) {
    int e = (blockIdx.x * blockDim.x + threadIdx.x) * 2;
    if (e >= N_EDGES) return;
    int r0, r1;
    if (g_is64) {
        longlong2 rr = __ldg((const longlong2*)((const long long*)eiv + e));
        r0 = (int)rr.x; r1 = (int)rr.y;
    } else {
        int2 rr = __ldg((const int2*)((const int*)eiv + e));
        r0 = rr.x; r1 = rr.y;
    }
    if (r0 >= 0 && r0 < N_NODES) atomicAdd(&g_deg[r0], 1);
    if (e + 1 < N_EDGES && r1 >= 0 && r1 < N_NODES) atomicAdd(&g_deg[r1], 1);
}

// ---------------- device-wide scan, level 1: per-block sums ---------------
__global__ void __launch_bounds__(1024) k_scan1() {
    __shared__ int red[32];
    int i = blockIdx.x * 1024 + threadIdx.x;
    int d = (i < N_NODES) ? g_deg[i] : 0;
    int s = d;
    #pragma unroll
    for (int o = 16; o > 0; o >>= 1) s += __shfl_down_sync(0xffffffffu, s, o);
    if ((threadIdx.x & 31) == 0) red[threadIdx.x >> 5] = s;
    __syncthreads();
    if (threadIdx.x < 32) {
        int v = red[threadIdx.x];
        #pragma unroll
        for (int o = 16; o > 0; o >>= 1) v += __shfl_down_sync(0xffffffffu, v, o);
        if (threadIdx.x == 0) g_bsum[blockIdx.x] = v;
    }
}

// ---------------- level 2: exclusive scan of SCAN_B block sums ------------
__global__ void __launch_bounds__(128) k_scan2() {
    __shared__ int sh[128];
    int t = threadIdx.x;
    int v = (t < SCAN_B) ? g_bsum[t] : 0;
    sh[t] = v;
    __syncthreads();
    #pragma unroll
    for (int off = 1; off < 128; off <<= 1) {
        int u = (t >= off) ? sh[t - off] : 0;
        __syncthreads();
        sh[t] += u;
        __syncthreads();
    }
    if (t < SCAN_B) g_boff[t] = sh[t] - v;          // exclusive
    if (t == SCAN_B - 1) g_ptr[N_NODES] = sh[t];    // total edge count
}

// ------ level 3: local scan + apply -> ptr, fill, dinv, rdinv -------------
__global__ void __launch_bounds__(1024) k_scan3() {
    __shared__ int warp_sums[32];
    int t = threadIdx.x;
    int i = blockIdx.x * 1024 + t;
    int d = (i < N_NODES) ? g_deg[i] : 0;
    int incl = d;
    int lane = t & 31;
    #pragma unroll
    for (int o = 1; o < 32; o <<= 1) {
        int u = __shfl_up_sync(0xffffffffu, incl, o);
        if (lane >= o) incl += u;
    }
    if (lane == 31) warp_sums[t >> 5] = incl;
    __syncthreads();
    if (t < 32) {
        int v = warp_sums[t];
        #pragma unroll
        for (int o = 1; o < 32; o <<= 1) {
            int u = __shfl_up_sync(0xffffffffu, v, o);
            if (t >= o) v += u;
        }
        warp_sums[t] = v;
    }
    __syncthreads();
    int wbase = (t >= 32) ? warp_sums[(t >> 5) - 1] : 0;
    int excl = g_boff[blockIdx.x] + wbase + incl - d;
    if (i < N_NODES) {
        g_ptr[i]  = excl;
        g_fill[i] = excl;
        float df = (float)(d < 1 ? 1 : d);
        g_dinv[i]  = rsqrtf(df);
        g_rdinv[i] = sqrtf(df);
    }
}

// ---------------- build: scatter cols into CSR (2 edges / thread) ---------
// No weights, no dinv reads, 4-byte writes.
__global__ void k_scatter(const void* __restrict__ eiv) {
    int e = (blockIdx.x * blockDim.x + threadIdx.x) * 2;
    if (e >= N_EDGES) return;
    int r0, r1, c0, c1;
    if (g_is64) {
        longlong2 rr = __ldg((const longlong2*)((const long long*)eiv + e));
        longlong2 cc = __ldg((const longlong2*)((const long long*)eiv + N_EDGES + e));
        r0 = (int)rr.x; r1 = (int)rr.y; c0 = (int)cc.x; c1 = (int)cc.y;
    } else {
        int2 rr = __ldg((const int2*)((const int*)eiv + e));
        int2 cc = __ldg((const int2*)((const int*)eiv + N_EDGES + e));
        r0 = rr.x; r1 = rr.y; c0 = cc.x; c1 = cc.y;
    }
    if (r0 >= 0 && r0 < N_NODES && c0 >= 0 && c0 < N_NODES) {
        int slot = atomicAdd(&g_fill[r0], 1);
        g_ecol[slot] = c0;
    }
    if (e + 1 < N_EDGES && r1 >= 0 && r1 < N_NODES && c1 >= 0 && c1 < N_NODES) {
        int slot = atomicAdd(&g_fill[r1], 1);
        g_ecol[slot] = c1;
    }
}

// ---------------- y0 = x @ W^T (shared-staged x tile, fp16 out) -----------
#define GTILE 16
#define XROW 136   // padded row stride in floats
__global__ void __launch_bounds__(128) k_gemm(const float* __restrict__ x,
                                              const float* __restrict__ W) {
    __shared__ float sx[GTILE * XROW];   // 8.5 KB

    const int tid   = threadIdx.x;
    const int warp  = tid >> 5;
    const int lane  = tid & 31;
    const int o     = warp * 16 + (lane & 15);
    const int khalf = lane >> 4;          // 0 or 1

    float4 wr[16];
    const float4* Wv = (const float4*)(W + o * HID + khalf * 64);
#pragma unroll
    for (int i = 0; i < 16; i++) wr[i] = Wv[i];

    const int base = blockIdx.x * GTILE;
    const float4* xg = (const float4*)(x + (long long)base * HID);
#pragma unroll
    for (int j = 0; j < 4; j++) {
        int f4 = tid + j * 128;                   // 0..511
        int t  = f4 >> 5;
        int k  = f4 & 31;
        float4 v = xg[f4];
        int word = t * XROW + ((k < 16) ? (k * 4) : (68 + (k - 16) * 4));
        *(float4*)(sx + word) = v;
    }
    __syncthreads();

#pragma unroll 1
    for (int t = 0; t < GTILE; t++) {
        const float4* xv = (const float4*)(sx + t * XROW + khalf * 68);
        float ax = 0.f, ay = 0.f, az = 0.f, aw = 0.f;
#pragma unroll
        for (int i = 0; i < 16; i++) {
            float4 xi = xv[i];
            ax += xi.x * wr[i].x;
            ay += xi.y * wr[i].y;
            az += xi.z * wr[i].z;
            aw += xi.w * wr[i].w;
        }
        float s = (ax + ay) + (az + aw);
        s += __shfl_down_sync(0xffffffffu, s, 16);
        if (khalf == 0) g_y0[(base + t) * OUTD + o] = __float2half_rn(s);
    }
}

// ---------------- propagate cores (R10 structure, 4-deep pipeline) --------
// 16 lanes per node; lane l covers dims [4l, 4l+4) = one uint2.
// Tail batches use col = N_NODES -> the always-zero pad row.
#define PADC N_NODES

__device__ __forceinline__ void acc4(uint2 u, float w,
                                     float& ax, float& ay, float& az, float& aw) {
    float2 f0 = __half22float2(*(const __half2*)&u.x);
    float2 f1 = __half22float2(*(const __half2*)&u.y);
    ax = fmaf(w, f0.x, ax); ay = fmaf(w, f0.y, ay);
    az = fmaf(w, f1.x, az); aw = fmaf(w, f1.y, aw);
}

// layer 1: s = sum_c dinv[c]*y0[c]  (weighted: dinv gathered per edge)
__device__ __forceinline__ void prop_w(const __half* __restrict__ src,
                                       int beg, int end, int l,
                                       float& ax, float& ay,
                                       float& az, float& aw) {
    int n = end - beg;
    if (n <= 0) return;
    const uint2* __restrict__ sv = (const uint2*)src;

    int c0, c1, c2, c3;
    c0 = __ldg(&g_ecol[beg]);
    c1 = (beg + 1 < end) ? __ldg(&g_ecol[beg + 1]) : PADC;
    c2 = (beg + 2 < end) ? __ldg(&g_ecol[beg + 2]) : PADC;
    c3 = (beg + 3 < end) ? __ldg(&g_ecol[beg + 3]) : PADC;
    int e = beg + 4;
    int nb = (n + 3) >> 2;
#pragma unroll 1
    for (int b = 0; b < nb; b++) {
        uint2 u0 = __ldg(&sv[(unsigned)c0 * 16u + l]);
        uint2 u1 = __ldg(&sv[(unsigned)c1 * 16u + l]);
        uint2 u2 = __ldg(&sv[(unsigned)c2 * 16u + l]);
        uint2 u3 = __ldg(&sv[(unsigned)c3 * 16u + l]);
        float w0 = __ldg(&g_dinv[c0]);
        float w1 = __ldg(&g_dinv[c1]);
        float w2 = __ldg(&g_dinv[c2]);
        float w3 = __ldg(&g_dinv[c3]);
        int n0 = PADC, n1 = PADC, n2 = PADC, n3 = PADC;
        if (e     < end) n0 = __ldg(&g_ecol[e]);
        if (e + 1 < end) n1 = __ldg(&g_ecol[e + 1]);
        if (e + 2 < end) n2 = __ldg(&g_ecol[e + 2]);
        if (e + 3 < end) n3 = __ldg(&g_ecol[e + 3]);
        acc4(u0, w0, ax, ay, az, aw);
        acc4(u1, w1, ax, ay, az, aw);
        acc4(u2, w2, ax, ay, az, aw);
        acc4(u3, w3, ax, ay, az, aw);
        c0 = n0; c1 = n1; c2 = n2; c3 = n3;
        e += 4;
    }
}

// layers 2-3: s = sum_c z[c]  (unweighted)
__device__ __forceinline__ void prop_u(const __half* __restrict__ src,
                                       int beg, int end, int l,
                                       float& ax, float& ay,
                                       float& az, float& aw) {
    int n = end - beg;
    if (n <= 0) return;
    const uint2* __restrict__ sv = (const uint2*)src;

    int c0, c1, c2, c3;
    c0 = __ldg(&g_ecol[beg]);
    c1 = (beg + 1 < end) ? __ldg(&g_ecol[beg + 1]) : PADC;
    c2 = (beg + 2 < end) ? __ldg(&g_ecol[beg + 2]) : PADC;
    c3 = (beg + 3 < end) ? __ldg(&g_ecol[beg + 3]) : PADC;
    int e = beg + 4;
    int nb = (n + 3) >> 2;
#pragma unroll 1
    for (int b = 0; b < nb; b++) {
        uint2 u0 = __ldg(&sv[(unsigned)c0 * 16u + l]);
        uint2 u1 = __ldg(&sv[(unsigned)c1 * 16u + l]);
        uint2 u2 = __ldg(&sv[(unsigned)c2 * 16u + l]);
        uint2 u3 = __ldg(&sv[(unsigned)c3 * 16u + l]);
        int n0 = PADC, n1 = PADC, n2 = PADC, n3 = PADC;
        if (e     < end) n0 = __ldg(&g_ecol[e]);
        if (e + 1 < end) n1 = __ldg(&g_ecol[e + 1]);
        if (e + 2 < end) n2 = __ldg(&g_ecol[e + 2]);
        if (e + 3 < end) n3 = __ldg(&g_ecol[e + 3]);
        acc4(u0, 1.f, ax, ay, az, aw);
        acc4(u1, 1.f, ax, ay, az, aw);
        acc4(u2, 1.f, ax, ay, az, aw);
        acc4(u3, 1.f, ax, ay, az, aw);
        c0 = n0; c1 = n1; c2 = n2; c3 = n3;
        e += 4;
    }
}

__device__ __forceinline__ void store_h4(__half* dst, int idx,
                                         float ax, float ay, float az, float aw) {
    __half2 h0 = __floats2half2_rn(ax, ay);
    __half2 h1 = __floats2half2_rn(az, aw);
    uint2 o;
    o.x = *(const unsigned*)&h0;
    o.y = *(const unsigned*)&h1;
    *((uint2*)(dst) + idx) = o;
}

// layer 1: z1[v] = dinv[v]^2 * sum_c dinv[c]*y0[c]
__global__ void __launch_bounds__(256) k_prop1() {
    int gid = blockIdx.x * blockDim.x + threadIdx.x;
    int v = gid >> 4;
    int l = gid & 15;
    if (v >= N_NODES) return;
    float ax = 0.f, ay = 0.f, az = 0.f, aw = 0.f;
    prop_w(g_y0, g_ptr[v], g_ptr[v + 1], l, ax, ay, az, aw);
    float dv = g_dinv[v];
    float d2 = dv * dv;
    store_h4(g_z1, v * 16 + l, ax * d2, ay * d2, az * d2, aw * d2);
}

// layer 2: z2[v] = dinv[v]^2 * sum_c z1[c]
__global__ void __launch_bounds__(256) k_prop2() {
    int gid = blockIdx.x * blockDim.x + threadIdx.x;
    int v = gid >> 4;
    int l = gid & 15;
    if (v >= N_NODES) return;
    float ax = 0.f, ay = 0.f, az = 0.f, aw = 0.f;
    prop_u(g_z1, g_ptr[v], g_ptr[v + 1], l, ax, ay, az, aw);
    float dv = g_dinv[v];
    float d2 = dv * dv;
    store_h4(g_z2, v * 16 + l, ax * d2, ay * d2, az * d2, aw * d2);
}

// final: y3 = dinv[v]*sum_c z2[c];
// out = 0.25*(y0 + rdinv*z1 + rdinv*z2 + y3) + b
__global__ void __launch_bounds__(256) k_propf(const float* __restrict__ bvec,
                                               float* __restrict__ out) {
    int gid = blockIdx.x * blockDim.x + threadIdx.x;
    int v = gid >> 4;
    int l = gid & 15;
    if (v >= N_NODES) return;
    float ax = 0.f, ay = 0.f, az = 0.f, aw = 0.f;
    prop_u(g_z2, g_ptr[v], g_ptr[v + 1], l, ax, ay, az, aw);
    float dv = g_dinv[v];
    float rd = g_rdinv[v];
    uint2 u0 = *((const uint2*)g_y0 + v * 16 + l);
    uint2 u1 = *((const uint2*)g_z1 + v * 16 + l);
    uint2 u2 = *((const uint2*)g_z2 + v * 16 + l);
    float2 a0  = __half22float2(*(const __half2*)&u0.x);
    float2 a0h = __half22float2(*(const __half2*)&u0.y);
    float2 a1  = __half22float2(*(const __half2*)&u1.x);
    float2 a1h = __half22float2(*(const __half2*)&u1.y);
    float2 a2  = __half22float2(*(const __half2*)&u2.x);
    float2 a2h = __half22float2(*(const __half2*)&u2.y);
    float b0 = bvec[l * 4 + 0], b1 = bvec[l * 4 + 1];
    float b2 = bvec[l * 4 + 2], b3 = bvec[l * 4 + 3];
    float4 r;
    r.x = (a0.x  + rd * (a1.x  + a2.x)  + dv * ax) * 0.25f + b0;
    r.y = (a0.y  + rd * (a1.y  + a2.y)  + dv * ay) * 0.25f + b1;
    r.z = (a0h.x + rd * (a1h.x + a2h.x) + dv * az) * 0.25f + b2;
    r.w = (a0h.y + rd * (a1h.y + a2h.y) + dv * aw) * 0.25f + b3;
    *(float4*)(out + v * OUTD + l * 4) = r;
}

// ---------------- launcher ------------------------------------------------
extern "C" void kernel_launch(void* const* d_in, const int* in_sizes, int n_in,
                              void* d_out, int out_size) {
    const float* x = nullptr;
    const float* W = nullptr;
    const float* b = nullptr;
    const void*  ei = nullptr;
    for (int i = 0; i < n_in; i++) {
        long long s = in_sizes[i];
        if      (s == (long long)N_NODES * HID) x = (const float*)d_in[i];
        else if (s == (long long)OUTD * HID)    W = (const float*)d_in[i];
        else if (s == (long long)OUTD)          b = (const float*)d_in[i];
        else ei = d_in[i];
    }
    if (!x)  x  = (const float*)d_in[0];
    if (!ei) ei = d_in[1];
    if (!W)  W  = (const float*)d_in[2];
    if (!b)  b  = (const float*)d_in[3];

    float* out = (float*)d_out;

    const int TB = 256;
    const int eb2 = (N_EDGES / 2 + TB - 1) / TB;  // 3125 (2 edges/thread)
    const int nb  = (N_NODES + TB - 1) / TB;      // 391
    const int pb  = (N_NODES * 16 + TB - 1) / TB; // 6250

    // Persistent side-stream handles: created ONCE on the first call (the
    // correctness run, outside capture); reused by every later call/capture.
    static cudaStream_t s2 = nullptr;
    static cudaEvent_t evFork = nullptr, evJoin = nullptr;
    if (!s2) {
        cudaStreamCreateWithFlags(&s2, cudaStreamNonBlocking);
        cudaEventCreateWithFlags(&evFork, cudaEventDisableTiming);
        cudaEventCreateWithFlags(&evJoin, cudaEventDisableTiming);
    }

    // Fork: GEMM overlaps the CSR build.
    cudaEventRecord(evFork, 0);
    cudaStreamWaitEvent(s2, evFork, 0);
    k_gemm<<<N_NODES / GTILE, 128, 0, s2>>>(x, W);   // y0 = x @ W^T
    cudaEventRecord(evJoin, s2);

    // CSR build on the main stream (overlaps with GEMM)
    k_init<<<nb, TB>>>((const unsigned long long*)ei);  // zero deg + dtype probe
    k_hist<<<eb2, TB>>>(ei);
    k_scan1<<<SCAN_B, 1024>>>();                        // per-block sums
    k_scan2<<<1, 128>>>();                              // scan of block sums
    k_scan3<<<SCAN_B, 1024>>>();                        // ptr+fill+dinv+rdinv
    k_scatter<<<eb2, TB>>>(ei);

    cudaStreamWaitEvent(0, evJoin, 0);       // join: props need y0 + CSR

    // 3 propagation layers in 64-dim fp16 z-space
    k_prop1<<<pb, TB>>>();            // z1 = dinv^2 * P'(y0)
    k_prop2<<<pb, TB>>>();            // z2 = dinv^2 * sum z1
    k_propf<<<pb, TB>>>(b, out);      // out = mean(y0..y3) + b
}